// round 1
// baseline (speedup 1.0000x reference)
#include <cuda_runtime.h>
#include <cstdint>

// Problem constants
#define NVAR  64
#define HID1  256
#define HID2  128
#define BATCH 16384
#define BT    128                   // batch rows per CTA
#define NCTA  (BATCH / BT)          // 128 CTAs
#define KT1   9                     // L1 K-tiles: K padded 65 -> 72 (u at k=64)
#define CHN   64                    // hidden chunk width (L1 N-chunk == L2 K-chunk)
#define NCH   4                     // HID1 / CHN
#define W1F_CHUNK (8 * KT1 * 64)    // 4608 floats: [nt=8][kt=9][lane=32][2]
#define W2F_CHUNK (16 * 8 * 64)     // 8192 floats: [nt=16][kt=8][lane=32][2]
#define SYS   76                    // SMEM row stride (conflict-free: 12r+c mod 32)

// Scratch (device globals: allocation-free rule)
__device__ float g_W1f[NVAR * NCH * W1F_CHUNK];   // ~4.7 MB, mask+u folded, frag-major, tf32-rounded
__device__ float g_W2f[NVAR * NCH * W2F_CHUNK];   // ~8.4 MB, frag-major, tf32-rounded
__device__ float g_Ut[NVAR * BATCH];              // U transposed

static __device__ __forceinline__ unsigned tf32u(float x) {
    unsigned r;
    asm("cvt.rna.tf32.f32 %0, %1;" : "=r"(r) : "f"(x));
    return r;
}
static __device__ __forceinline__ float tf32f(float x) { return __uint_as_float(tf32u(x)); }

static __device__ __forceinline__ void mma8(float* c,
                                            unsigned a0, unsigned a1, unsigned a2, unsigned a3,
                                            unsigned b0, unsigned b1) {
    asm volatile(
        "mma.sync.aligned.m16n8k8.row.col.f32.tf32.tf32.f32 "
        "{%0,%1,%2,%3},{%4,%5,%6,%7},{%8,%9},{%0,%1,%2,%3};\n"
        : "+f"(c[0]), "+f"(c[1]), "+f"(c[2]), "+f"(c[3])
        : "r"(a0), "r"(a1), "r"(a2), "r"(a3), "r"(b0), "r"(b1));
}

static __device__ __forceinline__ void cp16(float* sdst, const float* gsrc) {
    unsigned sa = (unsigned)__cvta_generic_to_shared(sdst);
    asm volatile("cp.async.cg.shared.global [%0], [%1], 16;\n" :: "r"(sa), "l"(gsrc));
}

// ---------------- prep kernels ----------------
// W1 frag-major, with causal mask folded into rows j<64, u-weights at j=64, zeros j=65..71.
__global__ void sen_prep_w1f(const float* __restrict__ W1, const int* __restrict__ G) {
    int idx = blockIdx.x * blockDim.x + threadIdx.x;
    if (idx >= NVAR * NCH * W1F_CHUNK) return;
    int cidx = idx / W1F_CHUNK;
    int f    = idx - cidx * W1F_CHUNK;
    int v    = cidx / NCH;
    int kc   = cidx - v * NCH;
    int p    = f & 1;
    int lane = (f >> 1) & 31;
    int q    = f >> 6;            // nt*KT1 + kt
    int kt   = q % KT1;
    int nt   = q / KT1;
    int j = kt * 8 + (lane & 3) + 4 * p;       // input-feature (K) index
    int h = kc * CHN + nt * 8 + (lane >> 2);   // hidden (N) index
    float val = 0.f;
    if (j < NVAR) {
        if (G[j * NVAR + v] > 0) val = tf32f(W1[(v * (NVAR + 1) + j) * HID1 + h]);
    } else if (j == NVAR) {
        val = tf32f(W1[(v * (NVAR + 1) + NVAR) * HID1 + h]);  // u weights
    }
    g_W1f[idx] = val;
}

__global__ void sen_prep_w2f(const float* __restrict__ W2) {
    int idx = blockIdx.x * blockDim.x + threadIdx.x;
    if (idx >= NVAR * NCH * W2F_CHUNK) return;
    int cidx = idx / W2F_CHUNK;
    int f    = idx - cidx * W2F_CHUNK;
    int v    = cidx / NCH;
    int kc   = cidx - v * NCH;
    int p    = f & 1;
    int lane = (f >> 1) & 31;
    int q    = f >> 6;            // nt*8 + kt
    int kt   = q & 7;
    int nt   = q >> 3;
    int k = kc * CHN + kt * 8 + (lane & 3) + 4 * p;
    int n = nt * 8 + (lane >> 2);
    g_W2f[idx] = tf32f(W2[(v * HID1 + k) * HID2 + n]);
}

__global__ void sen_prep_ut(const float* __restrict__ U) {
    int idx = blockIdx.x * blockDim.x + threadIdx.x;
    if (idx >= NVAR * BATCH) return;
    int v = idx / BATCH;
    int b = idx - v * BATCH;
    g_Ut[idx] = U[b * NVAR + v];
}

// ---------------- main persistent kernel ----------------
__global__ void __launch_bounds__(256, 1) sen_main(
    const float* __restrict__ X,
    const float* __restrict__ b1g,
    const float* __restrict__ b2g,
    const float* __restrict__ W3g,
    const float* __restrict__ b3g,
    float* __restrict__ out)
{
    extern __shared__ float sm[];
    float* sY  = sm;                          // [128][76]: Y tile, col 64 = u, cols 65..71 = 0
    float* sH  = sY  + BT * SYS;              // [128][76]: h1 chunk (tf32-rounded)
    float* sW1 = sH  + BT * SYS;              // 2 x 4608 (double buffer)
    float* sW2 = sW1 + 2 * W1F_CHUNK;         // 2 x 8192
    float* sB1 = sW2 + 2 * W2F_CHUNK;         // 2 x 256
    float* sB2 = sB1 + 2 * 256;               // 2 x 128
    float* sW3 = sB2 + 2 * 128;               // 2 x 128
    float* sB3 = sW3 + 2 * 128;               // 2

    const int tid  = threadIdx.x;
    const int lane = tid & 31;
    const int w    = tid >> 5;
    const int b0   = blockIdx.x * BT;
    const int rbase = 16 * w + (lane >> 2);   // warp owns rows [16w, 16w+16)

    // init Y tile from X; zero K-pad columns
    for (int idx = tid; idx < BT * 16; idx += 256) {
        int r = idx >> 4, c4 = idx & 15;
        *(float4*)(sY + r * SYS + c4 * 4) = *(const float4*)(X + (b0 + r) * NVAR + c4 * 4);
    }
    for (int idx = tid; idx < BT * 8; idx += 256) {
        int r = idx >> 3, c = 64 + (idx & 7);
        sY[r * SYS + c] = 0.f;
    }

    // prologue: prefetch chunk 0 weights + var-0 biases into buffer 0
    {
        const float* s1 = g_W1f;
        for (int idx = tid; idx < W1F_CHUNK / 4; idx += 256) cp16(sW1 + idx * 4, s1 + idx * 4);
        const float* s2 = g_W2f;
        for (int idx = tid; idx < W2F_CHUNK / 4; idx += 256) cp16(sW2 + idx * 4, s2 + idx * 4);
        sB1[tid] = __ldg(b1g + tid);
        if (tid < 128) { sB2[tid] = __ldg(b2g + tid); sW3[tid] = __ldg(W3g + tid); }
        if (tid == 0) sB3[0] = __ldg(b3g);
        asm volatile("cp.async.commit_group;\n" ::: "memory");
    }

    float acc2[64];  // L2 accumulators: 16 n-tiles x 4 regs (16 rows x 128 cols per warp)
    #pragma unroll
    for (int q = 0; q < 64; ++q) acc2[q] = 0.f;

    #pragma unroll 1
    for (int i = 0; i < NVAR; ++i) {
        const int pb = i & 1;
        // stage this variable's u into column 64 of OWN rows (no cross-warp dep)
        if (lane < 16) sY[(16 * w + lane) * SYS + 64] = g_Ut[i * BATCH + b0 + 16 * w + lane];
        __syncwarp();

        #pragma unroll 1
        for (int kc = 0; kc < NCH; ++kc) {
            const int c   = i * NCH + kc;
            const int cur = c & 1;
            __syncthreads();   // everyone done reading buffer (cur^1) from previous chunk

            // prefetch next chunk into the other buffer
            if (c + 1 < NVAR * NCH) {
                const int nxt = cur ^ 1;
                const float* s1 = g_W1f + (size_t)(c + 1) * W1F_CHUNK;
                float* d1 = sW1 + nxt * W1F_CHUNK;
                for (int idx = tid; idx < W1F_CHUNK / 4; idx += 256) cp16(d1 + idx * 4, s1 + idx * 4);
                const float* s2 = g_W2f + (size_t)(c + 1) * W2F_CHUNK;
                float* d2 = sW2 + nxt * W2F_CHUNK;
                for (int idx = tid; idx < W2F_CHUNK / 4; idx += 256) cp16(d2 + idx * 4, s2 + idx * 4);
                if (kc == 3) {   // next variable's biases (other parity buffer)
                    const int ip = i + 1, qb = pb ^ 1;
                    sB1[qb * 256 + tid] = __ldg(b1g + ip * HID1 + tid);
                    if (tid < 128) {
                        sB2[qb * 128 + tid] = __ldg(b2g + ip * HID2 + tid);
                        sW3[qb * 128 + tid] = __ldg(W3g + ip * HID2 + tid);
                    }
                    if (tid == 0) sB3[qb] = __ldg(b3g + ip);
                }
            }
            asm volatile("cp.async.commit_group;\n" ::: "memory");
            asm volatile("cp.async.wait_group 1;\n" ::: "memory");
            __syncthreads();   // buffer `cur` fully landed for all threads

            // ---- Layer 1: h1[:, kc*64 .. +64) = relu(inp @ W1m + b1), K = 72 (incl. u) ----
            float c1[8][4];
            #pragma unroll
            for (int nt = 0; nt < 8; ++nt) { c1[nt][0] = 0.f; c1[nt][1] = 0.f; c1[nt][2] = 0.f; c1[nt][3] = 0.f; }
            const float* wb1 = sW1 + cur * W1F_CHUNK + lane * 2;
            #pragma unroll
            for (int kt = 0; kt < KT1; ++kt) {
                const int cc = kt * 8 + (lane & 3);
                unsigned a0 = tf32u(sY[rbase * SYS + cc]);
                unsigned a1 = tf32u(sY[(rbase + 8) * SYS + cc]);
                unsigned a2 = tf32u(sY[rbase * SYS + cc + 4]);
                unsigned a3 = tf32u(sY[(rbase + 8) * SYS + cc + 4]);
                #pragma unroll
                for (int nt = 0; nt < 8; ++nt) {
                    float2 bb = *(const float2*)(wb1 + (nt * KT1 + kt) * 64);
                    mma8(c1[nt], a0, a1, a2, a3, __float_as_uint(bb.x), __float_as_uint(bb.y));
                }
            }
            // epilogue: +bias, relu, round to tf32, store h chunk
            {
                const float* B1 = sB1 + pb * 256 + kc * CHN;
                #pragma unroll
                for (int nt = 0; nt < 8; ++nt) {
                    const int col = nt * 8 + (lane & 3) * 2;
                    float bi0 = B1[col], bi1 = B1[col + 1];
                    float v0 = fmaxf(c1[nt][0] + bi0, 0.f);
                    float v1 = fmaxf(c1[nt][1] + bi1, 0.f);
                    float v2 = fmaxf(c1[nt][2] + bi0, 0.f);
                    float v3 = fmaxf(c1[nt][3] + bi1, 0.f);
                    *(float2*)(sH + rbase * SYS + col)       = make_float2(tf32f(v0), tf32f(v1));
                    *(float2*)(sH + (rbase + 8) * SYS + col) = make_float2(tf32f(v2), tf32f(v3));
                }
            }
            __syncthreads();

            // ---- Layer 2 partial: acc2 += h_chunk @ W2[kc*64.. , :] ----
            const float* wb2 = sW2 + cur * W2F_CHUNK + lane * 2;
            #pragma unroll
            for (int kt = 0; kt < 8; ++kt) {
                const int cc = kt * 8 + (lane & 3);
                unsigned a0 = __float_as_uint(sH[rbase * SYS + cc]);
                unsigned a1 = __float_as_uint(sH[(rbase + 8) * SYS + cc]);
                unsigned a2 = __float_as_uint(sH[rbase * SYS + cc + 4]);
                unsigned a3 = __float_as_uint(sH[(rbase + 8) * SYS + cc + 4]);
                #pragma unroll
                for (int nt = 0; nt < 16; ++nt) {
                    float2 bb = *(const float2*)(wb2 + (nt * 8 + kt) * 64);
                    mma8(&acc2[nt * 4], a0, a1, a2, a3, __float_as_uint(bb.x), __float_as_uint(bb.y));
                }
            }
        } // kc

        // ---- Layer 3: y = relu(acc2 + b2) @ w3 + b3; write Y[:, i] (own rows only) ----
        {
            float p0 = 0.f, p1 = 0.f;
            const float* B2 = sB2 + pb * 128;
            const float* w3 = sW3 + pb * 128;
            #pragma unroll
            for (int nt = 0; nt < 16; ++nt) {
                const int col = nt * 8 + (lane & 3) * 2;
                float w30 = w3[col], w31 = w3[col + 1];
                float bb0 = B2[col], bb1 = B2[col + 1];
                p0 += fmaxf(acc2[nt * 4 + 0] + bb0, 0.f) * w30;
                p0 += fmaxf(acc2[nt * 4 + 1] + bb1, 0.f) * w31;
                p1 += fmaxf(acc2[nt * 4 + 2] + bb0, 0.f) * w30;
                p1 += fmaxf(acc2[nt * 4 + 3] + bb1, 0.f) * w31;
                acc2[nt * 4 + 0] = 0.f; acc2[nt * 4 + 1] = 0.f;
                acc2[nt * 4 + 2] = 0.f; acc2[nt * 4 + 3] = 0.f;
            }
            p0 += __shfl_xor_sync(0xffffffffu, p0, 1);
            p0 += __shfl_xor_sync(0xffffffffu, p0, 2);
            p1 += __shfl_xor_sync(0xffffffffu, p1, 1);
            p1 += __shfl_xor_sync(0xffffffffu, p1, 2);
            if ((lane & 3) == 0) {
                float b3v = sB3[pb];
                sY[rbase * SYS + i]       = p0 + b3v;   // full fp32 kept for output
                sY[(rbase + 8) * SYS + i] = p1 + b3v;
            }
            __syncwarp();
        }
    } // i

    __syncthreads();
    for (int idx = tid; idx < BT * 16; idx += 256) {
        int r = idx >> 4, c4 = idx & 15;
        *(float4*)(out + (b0 + r) * NVAR + c4 * 4) = *(const float4*)(sY + r * SYS + c4 * 4);
    }
}

// ---------------- launch ----------------
extern "C" void kernel_launch(void* const* d_in, const int* in_sizes, int n_in,
                              void* d_out, int out_size) {
    (void)in_sizes; (void)n_in; (void)out_size;
    const float* X  = (const float*)d_in[0];
    const float* U  = (const float*)d_in[1];
    const int*   G  = (const int*)  d_in[2];
    const float* W1 = (const float*)d_in[3];
    const float* b1 = (const float*)d_in[4];
    const float* W2 = (const float*)d_in[5];
    const float* b2 = (const float*)d_in[6];
    const float* W3 = (const float*)d_in[7];
    const float* b3 = (const float*)d_in[8];
    float* out = (float*)d_out;

    const int n1 = NVAR * NCH * W1F_CHUNK;
    sen_prep_w1f<<<(n1 + 255) / 256, 256>>>(W1, G);
    const int n2 = NVAR * NCH * W2F_CHUNK;
    sen_prep_w2f<<<(n2 + 255) / 256, 256>>>(W2);
    const int n3 = NVAR * BATCH;
    sen_prep_ut<<<(n3 + 255) / 256, 256>>>(U);

    const size_t smem_floats = (size_t)BT * SYS * 2          // sY + sH
                             + 2 * W1F_CHUNK + 2 * W2F_CHUNK // weight double buffers
                             + 2 * 256 + 2 * 128 + 2 * 128 + 2;
    const size_t smem_bytes = smem_floats * sizeof(float);   // 184,328 B
    cudaFuncSetAttribute(sen_main, cudaFuncAttributeMaxDynamicSharedMemorySize, (int)smem_bytes);
    sen_main<<<NCTA, 256, smem_bytes>>>(X, b1, b2, W3, b3, out);
}